// round 1
// baseline (speedup 1.0000x reference)
#include <cuda_runtime.h>

// ---------------------------------------------------------------------------
// Problem constants
//   B=64, S=20, E=512, H=512, V=32000, C=1000
//   D1 = S*E + 2*E = 11264, 4H = 2048
// ---------------------------------------------------------------------------
#define Bsz   64
#define Hdim  512
#define G4H   2048
#define D1dim 11264
#define Vdim  32000

// Scratch (device globals — allocation-free per harness rules)
static __device__ float g_x[Bsz * D1dim];              // 2.9 MB
static __device__ float g_zpart[20 * Bsz * G4H];       // 10.5 MB (max 17 split slices)
static __device__ float g_hbuf[2][Bsz * Hdim];
static __device__ float g_cbuf[2][Bsz * Hdim];
static __device__ float g_logits[2 * Bsz * Vdim];      // 16.4 MB (2 split-K slices)

// ---------------------------------------------------------------------------
// f32x2 packed helpers (SASS FFMA2 path — 2x fp32 FMA throughput)
// ---------------------------------------------------------------------------
__device__ __forceinline__ unsigned long long pack2(float lo, float hi) {
    unsigned long long r;
    asm("mov.b64 %0, {%1, %2};" : "=l"(r) : "f"(lo), "f"(hi));
    return r;
}
__device__ __forceinline__ void unpack2(unsigned long long v, float& lo, float& hi) {
    asm("mov.b64 {%0, %1}, %2;" : "=f"(lo), "=f"(hi) : "l"(v));
}
__device__ __forceinline__ void fma2(unsigned long long& d, unsigned long long a,
                                     unsigned long long b) {
    asm("fma.rn.f32x2 %0, %1, %2, %0;" : "+l"(d) : "l"(a), "l"(b));
}

__device__ __forceinline__ float sigmoidf_fast(float x) {
    return 1.0f / (1.0f + __expf(-x));
}

// ---------------------------------------------------------------------------
// Build x = [enc_flat | word_embedding | persona[speaker]]   (64 x 11264)
// ---------------------------------------------------------------------------
__global__ void build_x_kernel(const float* __restrict__ enc,
                               const float* __restrict__ word,
                               const float* __restrict__ persona,
                               const int* __restrict__ speaker,
                               float* __restrict__ xout) {
    int idx = blockIdx.x * 256 + threadIdx.x;
    if (idx >= Bsz * D1dim) return;
    int b = idx / D1dim;
    int k = idx - b * D1dim;
    float v;
    if (k < 10240)       v = enc[b * 10240 + k];
    else if (k < 10752)  v = word[b * 512 + (k - 10240)];
    else                 v = persona[speaker[b] * 512 + (k - 10752)];
    xout[idx] = v;
}

// ---------------------------------------------------------------------------
// Split-K partial GEMM:  Zp[sp][m][n] = sum_{k in chunk} X[m][k] * W[k][n]
//   M = 64 (full batch), tile N = 128, BK = 16.
//   Handles two (X, W) matrix pairs: split indices [0, s1) use pair 1 with
//   chunk kc1; [s1, gridDim.y) use pair 2 with chunk kc2.
//   Requirements (all satisfied by our shapes): kc % 16 == 0, N % 128 == 0.
//   256 threads, 8x4 micro-tile as f32x2 pairs, double-buffered smem.
// ---------------------------------------------------------------------------
__global__ __launch_bounds__(256, 2) void gemm_partial_kernel(
    const float* __restrict__ X1, const float* __restrict__ Wm1, int ldx1, int s1, int kc1,
    const float* __restrict__ X2, const float* __restrict__ Wm2, int ldx2, int kc2,
    int N, float* __restrict__ Zp)
{
    __shared__ __align__(16) float Xs[2][16][68];   // [buf][k][m], stride 68 keeps 16B align
    __shared__ __align__(16) float Ws[2][16][128];  // [buf][k][n]

    const int tid = threadIdx.x;
    const int tx = tid & 31;        // col group: cols tx*4 .. tx*4+3
    const int ty = tid >> 5;        // row group: rows ty*8 .. ty*8+7
    const int n0 = blockIdx.x * 128;
    const int sp = blockIdx.y;

    const float* X;
    const float* Wm;
    int ldx, k0, kc;
    if (sp < s1) { X = X1; Wm = Wm1; ldx = ldx1; kc = kc1; k0 = sp * kc1; }
    else         { X = X2; Wm = Wm2; ldx = ldx2; kc = kc2; k0 = (sp - s1) * kc2; }

    // loader mapping
    const int xr = tid >> 2;            // 0..63 (batch row)
    const int xq = (tid & 3) * 4;       // k sub-offset 0,4,8,12
    const float* xptr = X + (long long)xr * ldx + k0 + xq;
    const int wrow = tid >> 5;          // 0..7
    const int wc = (tid & 31) * 4;
    const float* wptrA = Wm + (long long)(k0 + wrow) * N + n0 + wc;

    // preload tile 0
    float4 px  = *reinterpret_cast<const float4*>(xptr);
    float4 pw0 = *reinterpret_cast<const float4*>(wptrA);
    float4 pw1 = *reinterpret_cast<const float4*>(wptrA + 8LL * N);
    Xs[0][xq + 0][xr] = px.x;
    Xs[0][xq + 1][xr] = px.y;
    Xs[0][xq + 2][xr] = px.z;
    Xs[0][xq + 3][xr] = px.w;
    *reinterpret_cast<float4*>(&Ws[0][wrow][wc])     = pw0;
    *reinterpret_cast<float4*>(&Ws[0][wrow + 8][wc]) = pw1;
    __syncthreads();

    unsigned long long acc[4][4];
#pragma unroll
    for (int i = 0; i < 4; i++)
#pragma unroll
        for (int j = 0; j < 4; j++) acc[i][j] = 0ULL;

    const int ntiles = kc / 16;
    int buf = 0;
    for (int t = 0; t < ntiles; t++) {
        const bool has_next = (t + 1 < ntiles);
        if (has_next) {
            const float* xp2 = xptr + (t + 1) * 16;
            px = *reinterpret_cast<const float4*>(xp2);
            const float* wp2 = wptrA + (long long)(t + 1) * 16 * N;
            pw0 = *reinterpret_cast<const float4*>(wp2);
            pw1 = *reinterpret_cast<const float4*>(wp2 + 8LL * N);
        }
#pragma unroll
        for (int kk = 0; kk < 16; kk++) {
            ulonglong2 xa = *reinterpret_cast<const ulonglong2*>(&Xs[buf][kk][ty * 8]);
            ulonglong2 xb = *reinterpret_cast<const ulonglong2*>(&Xs[buf][kk][ty * 8 + 4]);
            float4 wv = *reinterpret_cast<const float4*>(&Ws[buf][kk][tx * 4]);
            unsigned long long w0 = pack2(wv.x, wv.x);
            unsigned long long w1 = pack2(wv.y, wv.y);
            unsigned long long w2 = pack2(wv.z, wv.z);
            unsigned long long w3 = pack2(wv.w, wv.w);
            fma2(acc[0][0], xa.x, w0); fma2(acc[0][1], xa.x, w1);
            fma2(acc[0][2], xa.x, w2); fma2(acc[0][3], xa.x, w3);
            fma2(acc[1][0], xa.y, w0); fma2(acc[1][1], xa.y, w1);
            fma2(acc[1][2], xa.y, w2); fma2(acc[1][3], xa.y, w3);
            fma2(acc[2][0], xb.x, w0); fma2(acc[2][1], xb.x, w1);
            fma2(acc[2][2], xb.x, w2); fma2(acc[2][3], xb.x, w3);
            fma2(acc[3][0], xb.y, w0); fma2(acc[3][1], xb.y, w1);
            fma2(acc[3][2], xb.y, w2); fma2(acc[3][3], xb.y, w3);
        }
        __syncthreads();
        if (has_next) {
            int nb = buf ^ 1;
            Xs[nb][xq + 0][xr] = px.x;
            Xs[nb][xq + 1][xr] = px.y;
            Xs[nb][xq + 2][xr] = px.z;
            Xs[nb][xq + 3][xr] = px.w;
            *reinterpret_cast<float4*>(&Ws[nb][wrow][wc])     = pw0;
            *reinterpret_cast<float4*>(&Ws[nb][wrow + 8][wc]) = pw1;
            buf = nb;
        }
        __syncthreads();
    }

    // epilogue: acc[rp][c] = rows (ty*8+2rp, ty*8+2rp+1), col tx*4+c
    float* zbase = Zp + ((long long)sp * 64 + ty * 8) * N + n0 + tx * 4;
#pragma unroll
    for (int rp = 0; rp < 4; rp++) {
        float lo[4], hi[4];
#pragma unroll
        for (int c = 0; c < 4; c++) unpack2(acc[rp][c], lo[c], hi[c]);
        float4 v0 = make_float4(lo[0], lo[1], lo[2], lo[3]);
        float4 v1 = make_float4(hi[0], hi[1], hi[2], hi[3]);
        *reinterpret_cast<float4*>(zbase + (long long)(2 * rp) * N)     = v0;
        *reinterpret_cast<float4*>(zbase + (long long)(2 * rp + 1) * N) = v1;
    }
}

// ---------------------------------------------------------------------------
// Gate kernel: reduce split-K slices + bias, apply Keras LSTM cell
//   (gate order i,f,g,o; activation=relu, recurrent_activation=sigmoid)
// ---------------------------------------------------------------------------
__global__ void gates_kernel(const float* __restrict__ Zp, int nsl,
                             const float* __restrict__ bias,
                             const float* __restrict__ c_prev,
                             float* __restrict__ h_new,
                             float* __restrict__ c_new)
{
    int idx = blockIdx.x * 256 + threadIdx.x;   // < 64*512
    if (idx >= Bsz * Hdim) return;
    int bt = idx >> 9;
    int j = idx & 511;
    float zi = bias[j], zf = bias[512 + j], zg = bias[1024 + j], zo = bias[1536 + j];
    const float* p = Zp + (long long)bt * G4H + j;
    for (int s = 0; s < nsl; s++) {
        zi += p[0];
        zf += p[512];
        zg += p[1024];
        zo += p[1536];
        p += (long long)Bsz * G4H;
    }
    float cv = sigmoidf_fast(zf) * c_prev[idx] + sigmoidf_fast(zi) * fmaxf(zg, 0.0f);
    float hv = sigmoidf_fast(zo) * fmaxf(cv, 0.0f);
    c_new[idx] = cv;
    h_new[idx] = hv;
}

// ---------------------------------------------------------------------------
// Softmax over V=32000 per batch row. Logits come as 2 split-K slices + bias.
// Online max/sum pass, then normalize pass (recompute).
// ---------------------------------------------------------------------------
__global__ void softmax_kernel(const float* __restrict__ L,
                               const float* __restrict__ bd,
                               float* __restrict__ out)
{
    const int V = Vdim;
    int b = blockIdx.x;
    int tid = threadIdx.x;
    const float* r0 = L + (long long)b * V;
    const float* r1 = L + (long long)(Bsz + b) * V;

    float m = -1e30f, s = 0.0f;
    for (int v = tid; v < V; v += 256) {
        float val = r0[v] + r1[v] + bd[v];
        float nm = fmaxf(m, val);
        s = s * __expf(m - nm) + __expf(val - nm);
        m = nm;
    }
    __shared__ float sm[256], ss[256];
    sm[tid] = m;
    ss[tid] = s;
    __syncthreads();
    for (int st = 128; st > 0; st >>= 1) {
        if (tid < st) {
            float m2 = sm[tid + st], s2 = ss[tid + st];
            float nm = fmaxf(sm[tid], m2);
            ss[tid] = ss[tid] * __expf(sm[tid] - nm) + s2 * __expf(m2 - nm);
            sm[tid] = nm;
        }
        __syncthreads();
    }
    float M = sm[0];
    float Sinv = 1.0f / ss[0];
    for (int v = tid; v < V; v += 256) {
        float val = r0[v] + r1[v] + bd[v];
        out[(long long)b * V + v] = __expf(val - M) * Sinv;
    }
}

// ---------------------------------------------------------------------------
// Copy h4, c4 into output tail
// ---------------------------------------------------------------------------
__global__ void copy_tail_kernel(const float* __restrict__ h4,
                                 const float* __restrict__ c4,
                                 float* __restrict__ out)
{
    int i = blockIdx.x * 256 + threadIdx.x;
    const int n = Bsz * Hdim;
    if (i < n)            out[i] = h4[i];
    else if (i < 2 * n)   out[i] = c4[i - n];
}

// ---------------------------------------------------------------------------
// kernel_launch
// ---------------------------------------------------------------------------
extern "C" void kernel_launch(void* const* d_in, const int* in_sizes, int n_in,
                              void* d_out, int out_size)
{
    const float* enc     = (const float*)d_in[0];
    const float* word    = (const float*)d_in[1];
    const float* h0      = (const float*)d_in[2];
    const float* c0      = (const float*)d_in[3];
    const float* persona = (const float*)d_in[4];
    const float* W1      = (const float*)d_in[5];
    const float* U1      = (const float*)d_in[6];
    const float* b1      = (const float*)d_in[7];
    const float* W2      = (const float*)d_in[8];
    const float* U2      = (const float*)d_in[9];
    const float* b2      = (const float*)d_in[10];
    const float* W3      = (const float*)d_in[11];
    const float* U3      = (const float*)d_in[12];
    const float* b3      = (const float*)d_in[13];
    const float* W4      = (const float*)d_in[14];
    const float* U4      = (const float*)d_in[15];
    const float* b4      = (const float*)d_in[16];
    const float* Wd      = (const float*)d_in[17];
    const float* bd      = (const float*)d_in[18];
    const int*   speaker = (const int*)d_in[19];
    float* out = (float*)d_out;

    void *px, *pz, *ph, *pc, *pl;
    cudaGetSymbolAddress(&px, g_x);
    cudaGetSymbolAddress(&pz, g_zpart);
    cudaGetSymbolAddress(&ph, g_hbuf);
    cudaGetSymbolAddress(&pc, g_cbuf);
    cudaGetSymbolAddress(&pl, g_logits);
    float* xg = (float*)px;
    float* zp = (float*)pz;
    float* hb = (float*)ph;   // [2][64*512]
    float* cb = (float*)pc;
    float* lg = (float*)pl;
    float* h1b = hb;               // ping
    float* h2b = hb + Bsz * Hdim;  // pong
    float* c1b = cb;
    float* c2b = cb + Bsz * Hdim;

    // 1) build x
    build_x_kernel<<<(Bsz * D1dim + 255) / 256, 256>>>(enc, word, persona, speaker, xg);

    // 2) layer 1: z = x@W1 (16 splits of 704) + h0@U1 (1 split of 512)
    gemm_partial_kernel<<<dim3(G4H / 128, 17), 256>>>(
        xg, W1, D1dim, 16, 704,
        h0, U1, Hdim, 512,
        G4H, zp);
    gates_kernel<<<(Bsz * Hdim + 255) / 256, 256>>>(zp, 17, b1, c0, h1b, c1b);

    // 3) layers 2..4: z = h@W (4 splits of 128) + h@U (4 splits of 128)
    gemm_partial_kernel<<<dim3(G4H / 128, 8), 256>>>(
        h1b, W2, Hdim, 4, 128, h1b, U2, Hdim, 128, G4H, zp);
    gates_kernel<<<(Bsz * Hdim + 255) / 256, 256>>>(zp, 8, b2, c1b, h2b, c2b);

    gemm_partial_kernel<<<dim3(G4H / 128, 8), 256>>>(
        h2b, W3, Hdim, 4, 128, h2b, U3, Hdim, 128, G4H, zp);
    gates_kernel<<<(Bsz * Hdim + 255) / 256, 256>>>(zp, 8, b3, c2b, h1b, c1b);

    gemm_partial_kernel<<<dim3(G4H / 128, 8), 256>>>(
        h1b, W4, Hdim, 4, 128, h1b, U4, Hdim, 128, G4H, zp);
    gates_kernel<<<(Bsz * Hdim + 255) / 256, 256>>>(zp, 8, b4, c1b, h2b, c2b);
    // h4 = h2b, c4 = c2b

    // 4) decoder: logits = h4@Wd, split-K = 2 (slices in g_logits)
    gemm_partial_kernel<<<dim3(Vdim / 128, 2), 256>>>(
        h2b, Wd, Hdim, 2, 256,
        h2b, Wd, Hdim, 256,
        Vdim, lg);

    // 5) softmax -> probs at out[0 : 64*32000)
    softmax_kernel<<<Bsz, 256>>>(lg, bd, out);

    // 6) h4, c4 -> output tail
    copy_tail_kernel<<<(2 * Bsz * Hdim + 255) / 256, 256>>>(
        h2b, c2b, out + (long long)Bsz * Vdim);
}